// round 10
// baseline (speedup 1.0000x reference)
#include <cuda_runtime.h>
#include <cuda_bf16.h>
#include <cstdint>

#define N_NODES 100000
#define N_EDGES 1600000
#define IN_F    512
#define HID_F   128
#define N_CLS   64
#define QTR     25088            // quarter size (mult of 128 and 8)
#define HALFN   50176            // = 2*QTR; column split & gemm1 half split

// ---------------- device scratch (no allocations allowed) ----------------
__device__ __align__(16) float g_h1[(size_t)N_NODES * HID_F];
__device__ __align__(16) float g_h2[(size_t)N_NODES * HID_F];
__device__ __align__(16) float g_h3[(size_t)N_NODES * N_CLS];
__device__ int   g_deg[N_NODES + 1];
__device__ int   g_deg_lo[N_NODES];
__device__ int   g_rowptr[N_NODES + 1];
__device__ int   g_mid[N_NODES];
__device__ int   g_fill_lo[N_NODES];
__device__ int   g_fill_hi[N_NODES];
__device__ int2  g_edge[N_EDGES];                 // {col, float_bits(val)}
__device__ __align__(16) __nv_bfloat16 g_w1t_hi[HID_F * IN_F];   // [128][512]
__device__ __align__(16) __nv_bfloat16 g_w1t_lo[HID_F * IN_F];
__device__ __align__(16) __nv_bfloat16 g_w2t_hi[N_CLS * HID_F];  // [64][128]
__device__ __align__(16) __nv_bfloat16 g_w2t_lo[N_CLS * HID_F];

// ---------------- small helpers ----------------
__device__ __forceinline__ uint32_t smem_u32(const void* p) {
    uint32_t a;
    asm("{ .reg .u64 t; cvta.to.shared.u64 t, %1; cvt.u32.u64 %0, t; }" : "=r"(a) : "l"(p));
    return a;
}
__device__ __forceinline__ void cp16(uint32_t dst, const void* src) {
    asm volatile("cp.async.ca.shared.global [%0], [%1], 16;" :: "r"(dst), "l"(src));
}
#define CP_COMMIT() asm volatile("cp.async.commit_group;" ::: "memory")
#define CP_WAIT(n)  asm volatile("cp.async.wait_group %0;" :: "n"(n) : "memory")

__device__ __forceinline__ void mma_bf16(float* c, const uint32_t* a, const uint32_t* b) {
    asm volatile(
        "mma.sync.aligned.m16n8k16.row.col.f32.bf16.bf16.f32 "
        "{%0,%1,%2,%3}, {%4,%5,%6,%7}, {%8,%9}, {%0,%1,%2,%3};"
        : "+f"(c[0]), "+f"(c[1]), "+f"(c[2]), "+f"(c[3])
        : "r"(a[0]), "r"(a[1]), "r"(a[2]), "r"(a[3]), "r"(b[0]), "r"(b[1]));
}
__device__ __forceinline__ uint32_t pack_bf16x2(__nv_bfloat16 a, __nv_bfloat16 b) {
    __nv_bfloat162 p; p.x = a; p.y = b;
    return *reinterpret_cast<uint32_t*>(&p);
}
__device__ __forceinline__ uint32_t split2(float2 v, uint32_t& lo) {
    __nv_bfloat16 h0 = __float2bfloat16(v.x), h1 = __float2bfloat16(v.y);
    lo = pack_bf16x2(__float2bfloat16(v.x - __bfloat162float(h0)),
                     __float2bfloat16(v.y - __bfloat162float(h1)));
    return pack_bf16x2(h0, h1);
}

// ---------------- segmented CSR build ----------------
__global__ void zero_deg_kernel() {
    int i = blockIdx.x * blockDim.x + threadIdx.x;
    if (i <= N_NODES) g_deg[i] = 0;
    if (i < N_NODES)  g_deg_lo[i] = 0;
}
__global__ void count_kernel(const int* __restrict__ row, const int* __restrict__ col) {
    int e = blockIdx.x * blockDim.x + threadIdx.x;
    if (e < N_EDGES) {
        int r = row[e];
        atomicAdd(&g_deg[r], 1);
        if (col[e] < HALFN) atomicAdd(&g_deg_lo[r], 1);
    }
}
__global__ __launch_bounds__(1024) void scan_kernel() {
    __shared__ int wsum[32];
    int t = threadIdx.x;
    const int CH = (N_NODES + 1023) / 1024;  // 98
    int base = t * CH;
    int s = 0;
#pragma unroll 4
    for (int j = 0; j < CH; j++) {
        int i = base + j;
        if (i < N_NODES) s += g_deg[i];
    }
    int lane = t & 31, wid = t >> 5;
    int v = s;
#pragma unroll
    for (int d = 1; d < 32; d <<= 1) {
        int n = __shfl_up_sync(0xFFFFFFFF, v, d);
        if (lane >= d) v += n;
    }
    if (lane == 31) wsum[wid] = v;
    __syncthreads();
    if (wid == 0) {
        int w = wsum[lane];
#pragma unroll
        for (int d = 1; d < 32; d <<= 1) {
            int n = __shfl_up_sync(0xFFFFFFFF, w, d);
            if (lane >= d) w += n;
        }
        wsum[lane] = w;
    }
    __syncthreads();
    int run = v - s + (wid ? wsum[wid - 1] : 0);
    for (int j = 0; j < CH; j++) {
        int i = base + j;
        if (i < N_NODES) {
            int d = g_deg[i];
            int mid = run + g_deg_lo[i];
            g_rowptr[i]  = run;
            g_mid[i]     = mid;
            g_fill_lo[i] = run;
            g_fill_hi[i] = mid;
            run += d;
        }
    }
    if (t == 1023) g_rowptr[N_NODES] = N_EDGES;
}
__global__ void scatter_kernel(const int* __restrict__ row, const int* __restrict__ col,
                               const float* __restrict__ val) {
    int e = blockIdx.x * blockDim.x + threadIdx.x;
    if (e < N_EDGES) {
        int r = row[e];
        int c = col[e];
        int p = (c < HALFN) ? atomicAdd(&g_fill_lo[r], 1)
                            : atomicAdd(&g_fill_hi[r], 1);
        g_edge[p] = make_int2(c, __float_as_int(val[e]));
    }
}

// ---------------- weight prep: transpose + bf16 hi/lo split ----------------
__global__ void prep_w1t_kernel(const float* __restrict__ w1) {
    int idx = blockIdx.x * blockDim.x + threadIdx.x;
    if (idx < IN_F * HID_F) {
        int k = idx >> 7, n = idx & 127;
        float v = w1[idx];
        __nv_bfloat16 h = __float2bfloat16(v);
        float r = v - __bfloat162float(h);
        g_w1t_hi[n * IN_F + k] = h;
        g_w1t_lo[n * IN_F + k] = __float2bfloat16(r);
    }
}
__global__ void prep_w2t_kernel(const float* __restrict__ w2) {
    int idx = blockIdx.x * blockDim.x + threadIdx.x;
    if (idx < HID_F * N_CLS) {
        int k = idx >> 6, n = idx & 63;
        float v = w2[idx];
        __nv_bfloat16 h = __float2bfloat16(v);
        float r = v - __bfloat162float(h);
        g_w2t_hi[n * HID_F + k] = h;
        g_w2t_lo[n * HID_F + k] = __float2bfloat16(r);
    }
}

// ---------------- cp.async pipelined bf16-split GEMM (R7-best config) -------
#define BK  64
#define LDK 72
#define LDA 68

template <int BN, int K_TOTAL>
__global__ __launch_bounds__(256) void gemm_pipe_kernel(
    const float* __restrict__ X,
    const __nv_bfloat16* __restrict__ Wt_hi,
    const __nv_bfloat16* __restrict__ Wt_lo,
    const float* __restrict__ Bias,
    float* __restrict__ O,
    int row_base, int row_limit) {
    constexpr int NITER = K_TOTAL / BK;
    extern __shared__ char smraw[];
    float* Af = (float*)smraw;                                   // [2][128][LDA]
    __nv_bfloat16* Bh = (__nv_bfloat16*)(Af + 2 * 128 * LDA);    // [BN][LDK]
    __nv_bfloat16* Bl = Bh + BN * LDK;

    const int t = threadIdx.x;
    const int lane = t & 31;
    const int wid = t >> 5;
    const int warp_m = wid & 3;
    const int warp_n = wid >> 2;
    const int NT = BN / 16;
    const int n0 = warp_n * (BN / 2);
    const int row0 = row_base + blockIdx.x * 128;
    const int gq = lane >> 2;
    const int gc2 = (lane & 3) * 2;

    const uint32_t af_u = smem_u32(Af);
    const uint32_t bh_u = smem_u32(Bh);
    const uint32_t bl_u = smem_u32(Bl);

    auto issueA = [&](int s) {
        const int buf = s & 1;
        const int k0 = s * BK;
#pragma unroll
        for (int i = 0; i < 8; i++) {
            int idx = t + i * 256;
            int row = idx >> 4, c4 = (idx & 15) * 4;
            int gr = row0 + row;
            if (gr >= N_NODES) gr = N_NODES - 1;
            cp16(af_u + (uint32_t)(((buf * 128 + row) * LDA + c4) * 4),
                 X + (size_t)gr * K_TOTAL + k0 + c4);
        }
    };
    auto issueB = [&](int s) {
        const int k0 = s * BK;
        constexpr int BCH = BN * 8 / 256;
#pragma unroll
        for (int i = 0; i < BCH; i++) {
            int idx = t + i * 256;
            int row = idx >> 3, q = (idx & 7) * 8;
            cp16(bh_u + (uint32_t)((row * LDK + q) * 2),
                 Wt_hi + (size_t)row * K_TOTAL + k0 + q);
            cp16(bl_u + (uint32_t)((row * LDK + q) * 2),
                 Wt_lo + (size_t)row * K_TOTAL + k0 + q);
        }
    };

    float acc[2][BN / 16][4];
#pragma unroll
    for (int mt = 0; mt < 2; mt++)
#pragma unroll
        for (int nt = 0; nt < NT; nt++)
#pragma unroll
            for (int i = 0; i < 4; i++) acc[mt][nt][i] = 0.f;

    issueB(0); CP_COMMIT();
    issueA(0); CP_COMMIT();
    if (NITER > 1) { issueA(1); CP_COMMIT(); CP_WAIT(1); }
    else           { CP_WAIT(0); }
    __syncthreads();

    for (int c = 0; c < NITER; c++) {
        const int buf = c & 1;
#pragma unroll
        for (int ks = 0; ks < 4; ks++) {
            const int k = ks * 16;
            uint32_t ah[2][4], al[2][4];
#pragma unroll
            for (int mt = 0; mt < 2; mt++) {
                const int rb = buf * 128 + warp_m * 32 + mt * 16 + gq;
                const float* p0 = &Af[rb * LDA + k + gc2];
                float2 v0 = *(const float2*)(p0);
                float2 v1 = *(const float2*)(p0 + 8 * LDA);
                float2 v2 = *(const float2*)(p0 + 8);
                float2 v3 = *(const float2*)(p0 + 8 * LDA + 8);
                ah[mt][0] = split2(v0, al[mt][0]);
                ah[mt][1] = split2(v1, al[mt][1]);
                ah[mt][2] = split2(v2, al[mt][2]);
                ah[mt][3] = split2(v3, al[mt][3]);
            }
#pragma unroll
            for (int nt = 0; nt < NT; nt++) {
                const int nrow = n0 + nt * 8 + gq;
                const __nv_bfloat16* ph = &Bh[nrow * LDK + k + gc2];
                const __nv_bfloat16* pl = &Bl[nrow * LDK + k + gc2];
                uint32_t bh[2], bl[2];
                bh[0] = *(const uint32_t*)(ph);
                bh[1] = *(const uint32_t*)(ph + 8);
                bl[0] = *(const uint32_t*)(pl);
                bl[1] = *(const uint32_t*)(pl + 8);
#pragma unroll
                for (int mt = 0; mt < 2; mt++) {
                    mma_bf16(acc[mt][nt], ah[mt], bh);
                    mma_bf16(acc[mt][nt], ah[mt], bl);
                    mma_bf16(acc[mt][nt], al[mt], bh);
                }
            }
        }
        __syncthreads();
        if (c + 1 < NITER) {
            issueB(c + 1); CP_COMMIT();
            if (c + 2 < NITER) { issueA(c + 2); CP_COMMIT(); CP_WAIT(1); }
            else               { CP_WAIT(0); }
            __syncthreads();
        }
    }

#pragma unroll
    for (int nt = 0; nt < NT; nt++) {
        const int colb = n0 + nt * 8 + gc2;
        float2 bb = *(const float2*)&Bias[colb];
#pragma unroll
        for (int mt = 0; mt < 2; mt++) {
            int r0 = row0 + warp_m * 32 + mt * 16 + gq;
            if (r0 < row_limit) {
                float2 o0;
                o0.x = acc[mt][nt][0] + bb.x;
                o0.y = acc[mt][nt][1] + bb.y;
                *(float2*)&O[(size_t)r0 * BN + colb] = o0;
            }
            int r1 = r0 + 8;
            if (r1 < row_limit) {
                float2 o1;
                o1.x = acc[mt][nt][2] + bb.x;
                o1.y = acc[mt][nt][3] + bb.y;
                *(float2*)&O[(size_t)r1 * BN + colb] = o1;
            }
        }
    }
}

// ---------------- Segmented SpMM: each row's edges pre-sorted lo|hi ---------
// FINAL=false: lo segment [rowptr, mid)  -> raw partial (plain store)
// FINAL=true : hi segment [mid, rowptr+1) -> add partial (+ReLU for L1)
template <bool FINAL>
__global__ __launch_bounds__(256) void spmm1_seg_kernel(
    const float* __restrict__ h1, float* __restrict__ h2, int node_base) {
    int node = node_base + blockIdx.x * 8 + (threadIdx.x >> 5);
    int lane = threadIdx.x & 31;
    int s, e;
    if (FINAL) { s = g_mid[node]; e = g_rowptr[node + 1]; }
    else       { s = g_rowptr[node]; e = g_mid[node]; }

    float4 a0 = make_float4(0.f, 0.f, 0.f, 0.f);
    float4 a1 = a0, a2 = a0, a3 = a0;
    const float4* H = (const float4*)h1;

    int j = s;
    for (; j + 3 < e; j += 4) {
        int2 e0 = g_edge[j],     e1 = g_edge[j + 1];
        int2 e2 = g_edge[j + 2], e3 = g_edge[j + 3];
        float v0 = __int_as_float(e0.y), v1 = __int_as_float(e1.y);
        float v2 = __int_as_float(e2.y), v3 = __int_as_float(e3.y);
        float4 x0 = H[(size_t)e0.x * 32 + lane];
        float4 x1 = H[(size_t)e1.x * 32 + lane];
        float4 x2 = H[(size_t)e2.x * 32 + lane];
        float4 x3 = H[(size_t)e3.x * 32 + lane];
        a0.x += v0 * x0.x; a0.y += v0 * x0.y; a0.z += v0 * x0.z; a0.w += v0 * x0.w;
        a1.x += v1 * x1.x; a1.y += v1 * x1.y; a1.z += v1 * x1.z; a1.w += v1 * x1.w;
        a2.x += v2 * x2.x; a2.y += v2 * x2.y; a2.z += v2 * x2.z; a2.w += v2 * x2.w;
        a3.x += v3 * x3.x; a3.y += v3 * x3.y; a3.z += v3 * x3.z; a3.w += v3 * x3.w;
    }
    for (; j < e; j++) {
        int2 ed = g_edge[j];
        float v = __int_as_float(ed.y);
        float4 x = H[(size_t)ed.x * 32 + lane];
        a0.x += v * x.x; a0.y += v * x.y; a0.z += v * x.z; a0.w += v * x.w;
    }
    float4 o;
    o.x = a0.x + a1.x + a2.x + a3.x;
    o.y = a0.y + a1.y + a2.y + a3.y;
    o.z = a0.z + a1.z + a2.z + a3.z;
    o.w = a0.w + a1.w + a2.w + a3.w;
    if (FINAL) {
        float4 prev = ((const float4*)h2)[(size_t)node * 32 + lane];
        o.x = fmaxf(o.x + prev.x, 0.f);
        o.y = fmaxf(o.y + prev.y, 0.f);
        o.z = fmaxf(o.z + prev.z, 0.f);
        o.w = fmaxf(o.w + prev.w, 0.f);
    }
    ((float4*)h2)[(size_t)node * 32 + lane] = o;
}

template <bool FINAL>
__global__ __launch_bounds__(256) void spmm2_seg_kernel(
    const float* __restrict__ h3, float* __restrict__ out) {
    int node = blockIdx.x * 8 + (threadIdx.x >> 5);
    int lane = threadIdx.x & 31;
    int s, e;
    if (FINAL) { s = g_mid[node]; e = g_rowptr[node + 1]; }
    else       { s = g_rowptr[node]; e = g_mid[node]; }

    float2 a0 = make_float2(0.f, 0.f);
    float2 a1 = a0, a2 = a0, a3 = a0;
    const float2* H = (const float2*)h3;

    int j = s;
    for (; j + 3 < e; j += 4) {
        int2 e0 = g_edge[j],     e1 = g_edge[j + 1];
        int2 e2 = g_edge[j + 2], e3 = g_edge[j + 3];
        float v0 = __int_as_float(e0.y), v1 = __int_as_float(e1.y);
        float v2 = __int_as_float(e2.y), v3 = __int_as_float(e3.y);
        float2 x0 = H[(size_t)e0.x * 32 + lane];
        float2 x1 = H[(size_t)e1.x * 32 + lane];
        float2 x2 = H[(size_t)e2.x * 32 + lane];
        float2 x3 = H[(size_t)e3.x * 32 + lane];
        a0.x += v0 * x0.x; a0.y += v0 * x0.y;
        a1.x += v1 * x1.x; a1.y += v1 * x1.y;
        a2.x += v2 * x2.x; a2.y += v2 * x2.y;
        a3.x += v3 * x3.x; a3.y += v3 * x3.y;
    }
    for (; j < e; j++) {
        int2 ed = g_edge[j];
        float v = __int_as_float(ed.y);
        float2 x = H[(size_t)ed.x * 32 + lane];
        a0.x += v * x.x; a0.y += v * x.y;
    }
    float2 o;
    o.x = a0.x + a1.x + a2.x + a3.x;
    o.y = a0.y + a1.y + a2.y + a3.y;
    if (FINAL) {
        float2 prev = ((const float2*)out)[(size_t)node * 32 + lane];
        o.x += prev.x;
        o.y += prev.y;
    }
    ((float2*)out)[(size_t)node * 32 + lane] = o;
}

// ---------------- launch ----------------
#define SMEM_PIPE(BN) (2 * 128 * LDA * 4 + 2 * (BN) * LDK * 2)

extern "C" void kernel_launch(void* const* d_in, const int* in_sizes, int n_in,
                              void* d_out, int out_size) {
    const float* x       = (const float*)d_in[0];
    const int*   adj_row = (const int*)d_in[1];
    const int*   adj_col = (const int*)d_in[2];
    const float* adj_val = (const float*)d_in[3];
    const float* w1      = (const float*)d_in[4];
    const float* b1      = (const float*)d_in[5];
    const float* w2      = (const float*)d_in[6];
    const float* b2      = (const float*)d_in[7];
    float* out = (float*)d_out;

    float* h1 = nullptr; float* h2 = nullptr; float* h3 = nullptr;
    const __nv_bfloat16 *w1h, *w1l, *w2h, *w2l;
    cudaGetSymbolAddress((void**)&h1, g_h1);
    cudaGetSymbolAddress((void**)&h2, g_h2);
    cudaGetSymbolAddress((void**)&h3, g_h3);
    cudaGetSymbolAddress((void**)&w1h, g_w1t_hi);
    cudaGetSymbolAddress((void**)&w1l, g_w1t_lo);
    cudaGetSymbolAddress((void**)&w2h, g_w2t_hi);
    cudaGetSymbolAddress((void**)&w2l, g_w2t_lo);

    static cudaStream_t s1 = nullptr;
    static cudaEvent_t ev_fork, ev_g1h0, ev_s1p0, ev_q0, ev_q1, ev_q2, ev_q3,
                       ev_g2q1, ev_g2all;
    static bool init_done = false;
    if (!init_done) {
        cudaFuncSetAttribute(gemm_pipe_kernel<HID_F, IN_F>,
                             cudaFuncAttributeMaxDynamicSharedMemorySize, SMEM_PIPE(HID_F));
        cudaFuncSetAttribute(gemm_pipe_kernel<N_CLS, HID_F>,
                             cudaFuncAttributeMaxDynamicSharedMemorySize, SMEM_PIPE(N_CLS));
        cudaStreamCreateWithFlags(&s1, cudaStreamNonBlocking);
        cudaEventCreateWithFlags(&ev_fork,  cudaEventDisableTiming);
        cudaEventCreateWithFlags(&ev_g1h0,  cudaEventDisableTiming);
        cudaEventCreateWithFlags(&ev_s1p0,  cudaEventDisableTiming);
        cudaEventCreateWithFlags(&ev_q0,    cudaEventDisableTiming);
        cudaEventCreateWithFlags(&ev_q1,    cudaEventDisableTiming);
        cudaEventCreateWithFlags(&ev_q2,    cudaEventDisableTiming);
        cudaEventCreateWithFlags(&ev_q3,    cudaEventDisableTiming);
        cudaEventCreateWithFlags(&ev_g2q1,  cudaEventDisableTiming);
        cudaEventCreateWithFlags(&ev_g2all, cudaEventDisableTiming);
        init_done = true;
    }

    const int NBLK_ALL = N_NODES / 8;        // 12500
    const int QS[5] = {0, QTR, 2 * QTR, 3 * QTR, N_NODES};

    // ---- side stream: segmented CSR build (overlaps prep + gemm1_h0) ----
    cudaEventRecord(ev_fork, 0);
    cudaStreamWaitEvent(s1, ev_fork, 0);
    zero_deg_kernel<<<(N_NODES + 256) / 256, 256, 0, s1>>>();
    count_kernel<<<(N_EDGES + 255) / 256, 256, 0, s1>>>(adj_row, adj_col);
    scan_kernel<<<1, 1024, 0, s1>>>();
    scatter_kernel<<<(N_EDGES + 255) / 256, 256, 0, s1>>>(adj_row, adj_col, adj_val);

    // ---- main: weight prep + gemm1 halves ----
    prep_w1t_kernel<<<(IN_F * HID_F + 255) / 256, 256>>>(w1);
    prep_w2t_kernel<<<(HID_F * N_CLS + 255) / 256, 256>>>(w2);
    gemm_pipe_kernel<HID_F, IN_F>
        <<<HALFN / 128, 256, SMEM_PIPE(HID_F)>>>(x, w1h, w1l, b1, h1, 0, HALFN);
    cudaEventRecord(ev_g1h0, 0);
    gemm_pipe_kernel<HID_F, IN_F>
        <<<(N_NODES - HALFN + 127) / 128, 256, SMEM_PIPE(HID_F)>>>(
            x, w1h, w1l, b1, h1, HALFN, N_NODES);

    // ---- side: spmm1 pass0 (lo cols, only needs h1 rows < HALFN) ∥ gemm1_h1
    cudaStreamWaitEvent(s1, ev_g1h0, 0);
    spmm1_seg_kernel<false><<<NBLK_ALL, 256, 0, s1>>>(h1, h2, 0);
    cudaEventRecord(ev_s1p0, s1);

    // ---- main: spmm1 pass1 in row quarters; each feeds gemm2 on side ----
    cudaStreamWaitEvent(0, ev_s1p0, 0);
    spmm1_seg_kernel<true><<<(QS[1] - QS[0]) / 8, 256>>>(h1, h2, QS[0]);
    cudaEventRecord(ev_q0, 0);
    spmm1_seg_kernel<true><<<(QS[2] - QS[1]) / 8, 256>>>(h1, h2, QS[1]);
    cudaEventRecord(ev_q1, 0);
    spmm1_seg_kernel<true><<<(QS[3] - QS[2]) / 8, 256>>>(h1, h2, QS[2]);
    cudaEventRecord(ev_q2, 0);
    spmm1_seg_kernel<true><<<(QS[4] - QS[3]) / 8, 256>>>(h1, h2, QS[3]);
    cudaEventRecord(ev_q3, 0);

    cudaStreamWaitEvent(s1, ev_q0, 0);
    gemm_pipe_kernel<N_CLS, HID_F>
        <<<(QS[1] - QS[0] + 127) / 128, 256, SMEM_PIPE(N_CLS), s1>>>(
            h2, w2h, w2l, b2, h3, QS[0], QS[1]);
    cudaStreamWaitEvent(s1, ev_q1, 0);
    gemm_pipe_kernel<N_CLS, HID_F>
        <<<(QS[2] - QS[1] + 127) / 128, 256, SMEM_PIPE(N_CLS), s1>>>(
            h2, w2h, w2l, b2, h3, QS[1], QS[2]);
    cudaEventRecord(ev_g2q1, s1);          // h3 rows [0, HALFN) done
    cudaStreamWaitEvent(s1, ev_q2, 0);
    gemm_pipe_kernel<N_CLS, HID_F>
        <<<(QS[3] - QS[2] + 127) / 128, 256, SMEM_PIPE(N_CLS), s1>>>(
            h2, w2h, w2l, b2, h3, QS[2], QS[3]);
    cudaStreamWaitEvent(s1, ev_q3, 0);
    gemm_pipe_kernel<N_CLS, HID_F>
        <<<(QS[4] - QS[3] + 127) / 128, 256, SMEM_PIPE(N_CLS), s1>>>(
            h2, w2h, w2l, b2, h3, QS[3], QS[4]);
    cudaEventRecord(ev_g2all, s1);

    // ---- main: spmm2 pass0 (lo cols, needs h3 rows < HALFN) ∥ gemm2 q2/q3
    cudaStreamWaitEvent(0, ev_g2q1, 0);
    spmm2_seg_kernel<false><<<NBLK_ALL, 256>>>(h3, out);
    // ---- spmm2 pass1 (hi cols) finalizes ----
    cudaStreamWaitEvent(0, ev_g2all, 0);
    spmm2_seg_kernel<true><<<NBLK_ALL, 256>>>(h3, out);
}

// round 11
// speedup vs baseline: 1.0145x; 1.0145x over previous
#include <cuda_runtime.h>
#include <cuda_bf16.h>
#include <cstdint>

#define N_NODES 100000
#define N_EDGES 1600000
#define IN_F    512
#define HID_F   128
#define N_CLS   64
#define HALFN   50176            // row/col split, multiple of 128

// ---------------- device scratch (no allocations allowed) ----------------
__device__ __align__(16) float g_h1[(size_t)N_NODES * HID_F];
__device__ __align__(16) float g_h2[(size_t)N_NODES * HID_F];
__device__ __align__(16) float g_h3[(size_t)N_NODES * N_CLS];
__device__ int   g_deg[N_NODES + 1];
__device__ int   g_deg_lo[N_NODES];
__device__ int   g_rowptr[N_NODES + 1];
__device__ int   g_mid[N_NODES];
__device__ int   g_fill_lo[N_NODES];
__device__ int   g_fill_hi[N_NODES];
__device__ int2  g_edge[N_EDGES];                 // {col, float_bits(val)}
__device__ __align__(16) __nv_bfloat16 g_w1t_hi[HID_F * IN_F];   // [128][512]
__device__ __align__(16) __nv_bfloat16 g_w1t_lo[HID_F * IN_F];
__device__ __align__(16) __nv_bfloat16 g_w2t_hi[N_CLS * HID_F];  // [64][128]
__device__ __align__(16) __nv_bfloat16 g_w2t_lo[N_CLS * HID_F];

// ---------------- small helpers ----------------
__device__ __forceinline__ uint32_t smem_u32(const void* p) {
    uint32_t a;
    asm("{ .reg .u64 t; cvta.to.shared.u64 t, %1; cvt.u32.u64 %0, t; }" : "=r"(a) : "l"(p));
    return a;
}
__device__ __forceinline__ void cp16(uint32_t dst, const void* src) {
    asm volatile("cp.async.ca.shared.global [%0], [%1], 16;" :: "r"(dst), "l"(src));
}
#define CP_COMMIT() asm volatile("cp.async.commit_group;" ::: "memory")
#define CP_WAIT(n)  asm volatile("cp.async.wait_group %0;" :: "n"(n) : "memory")

__device__ __forceinline__ void mma_bf16(float* c, const uint32_t* a, const uint32_t* b) {
    asm volatile(
        "mma.sync.aligned.m16n8k16.row.col.f32.bf16.bf16.f32 "
        "{%0,%1,%2,%3}, {%4,%5,%6,%7}, {%8,%9}, {%0,%1,%2,%3};"
        : "+f"(c[0]), "+f"(c[1]), "+f"(c[2]), "+f"(c[3])
        : "r"(a[0]), "r"(a[1]), "r"(a[2]), "r"(a[3]), "r"(b[0]), "r"(b[1]));
}
__device__ __forceinline__ uint32_t pack_bf16x2(__nv_bfloat16 a, __nv_bfloat16 b) {
    __nv_bfloat162 p; p.x = a; p.y = b;
    return *reinterpret_cast<uint32_t*>(&p);
}
__device__ __forceinline__ uint32_t split2(float2 v, uint32_t& lo) {
    __nv_bfloat16 h0 = __float2bfloat16(v.x), h1 = __float2bfloat16(v.y);
    lo = pack_bf16x2(__float2bfloat16(v.x - __bfloat162float(h0)),
                     __float2bfloat16(v.y - __bfloat162float(h1)));
    return pack_bf16x2(h0, h1);
}

// ---------------- segmented CSR build ----------------
__global__ void zero_deg_kernel() {
    int i = blockIdx.x * blockDim.x + threadIdx.x;
    if (i <= N_NODES) g_deg[i] = 0;
    if (i < N_NODES)  g_deg_lo[i] = 0;
}
__global__ void count_kernel(const int* __restrict__ row, const int* __restrict__ col) {
    int e = blockIdx.x * blockDim.x + threadIdx.x;
    if (e < N_EDGES) {
        int r = row[e];
        atomicAdd(&g_deg[r], 1);
        if (col[e] < HALFN) atomicAdd(&g_deg_lo[r], 1);
    }
}
__global__ __launch_bounds__(1024) void scan_kernel() {
    __shared__ int wsum[32];
    int t = threadIdx.x;
    const int CH = (N_NODES + 1023) / 1024;  // 98
    int base = t * CH;
    int s = 0;
#pragma unroll 4
    for (int j = 0; j < CH; j++) {
        int i = base + j;
        if (i < N_NODES) s += g_deg[i];
    }
    int lane = t & 31, wid = t >> 5;
    int v = s;
#pragma unroll
    for (int d = 1; d < 32; d <<= 1) {
        int n = __shfl_up_sync(0xFFFFFFFF, v, d);
        if (lane >= d) v += n;
    }
    if (lane == 31) wsum[wid] = v;
    __syncthreads();
    if (wid == 0) {
        int w = wsum[lane];
#pragma unroll
        for (int d = 1; d < 32; d <<= 1) {
            int n = __shfl_up_sync(0xFFFFFFFF, w, d);
            if (lane >= d) w += n;
        }
        wsum[lane] = w;
    }
    __syncthreads();
    int run = v - s + (wid ? wsum[wid - 1] : 0);
    for (int j = 0; j < CH; j++) {
        int i = base + j;
        if (i < N_NODES) {
            int d = g_deg[i];
            int mid = run + g_deg_lo[i];
            g_rowptr[i]  = run;
            g_mid[i]     = mid;
            g_fill_lo[i] = run;
            g_fill_hi[i] = mid;
            run += d;
        }
    }
    if (t == 1023) g_rowptr[N_NODES] = N_EDGES;
}
__global__ void scatter_kernel(const int* __restrict__ row, const int* __restrict__ col,
                               const float* __restrict__ val) {
    int e = blockIdx.x * blockDim.x + threadIdx.x;
    if (e < N_EDGES) {
        int r = row[e];
        int c = col[e];
        int p = (c < HALFN) ? atomicAdd(&g_fill_lo[r], 1)
                            : atomicAdd(&g_fill_hi[r], 1);
        g_edge[p] = make_int2(c, __float_as_int(val[e]));
    }
}

// ---------------- weight prep: transpose + bf16 hi/lo split ----------------
__global__ void prep_w1t_kernel(const float* __restrict__ w1) {
    int idx = blockIdx.x * blockDim.x + threadIdx.x;
    if (idx < IN_F * HID_F) {
        int k = idx >> 7, n = idx & 127;
        float v = w1[idx];
        __nv_bfloat16 h = __float2bfloat16(v);
        float r = v - __bfloat162float(h);
        g_w1t_hi[n * IN_F + k] = h;
        g_w1t_lo[n * IN_F + k] = __float2bfloat16(r);
    }
}
__global__ void prep_w2t_kernel(const float* __restrict__ w2) {
    int idx = blockIdx.x * blockDim.x + threadIdx.x;
    if (idx < HID_F * N_CLS) {
        int k = idx >> 6, n = idx & 63;
        float v = w2[idx];
        __nv_bfloat16 h = __float2bfloat16(v);
        float r = v - __bfloat162float(h);
        g_w2t_hi[n * HID_F + k] = h;
        g_w2t_lo[n * HID_F + k] = __float2bfloat16(r);
    }
}

// ---------------- cp.async pipelined bf16-split GEMM (R7-best config) -------
#define BK  64
#define LDK 72
#define LDA 68

template <int BN, int K_TOTAL>
__global__ __launch_bounds__(256) void gemm_pipe_kernel(
    const float* __restrict__ X,
    const __nv_bfloat16* __restrict__ Wt_hi,
    const __nv_bfloat16* __restrict__ Wt_lo,
    const float* __restrict__ Bias,
    float* __restrict__ O,
    int row_base, int row_limit) {
    constexpr int NITER = K_TOTAL / BK;
    extern __shared__ char smraw[];
    float* Af = (float*)smraw;                                   // [2][128][LDA]
    __nv_bfloat16* Bh = (__nv_bfloat16*)(Af + 2 * 128 * LDA);    // [BN][LDK]
    __nv_bfloat16* Bl = Bh + BN * LDK;

    const int t = threadIdx.x;
    const int lane = t & 31;
    const int wid = t >> 5;
    const int warp_m = wid & 3;
    const int warp_n = wid >> 2;
    const int NT = BN / 16;
    const int n0 = warp_n * (BN / 2);
    const int row0 = row_base + blockIdx.x * 128;
    const int gq = lane >> 2;
    const int gc2 = (lane & 3) * 2;

    const uint32_t af_u = smem_u32(Af);
    const uint32_t bh_u = smem_u32(Bh);
    const uint32_t bl_u = smem_u32(Bl);

    auto issueA = [&](int s) {
        const int buf = s & 1;
        const int k0 = s * BK;
#pragma unroll
        for (int i = 0; i < 8; i++) {
            int idx = t + i * 256;
            int row = idx >> 4, c4 = (idx & 15) * 4;
            int gr = row0 + row;
            if (gr >= N_NODES) gr = N_NODES - 1;
            cp16(af_u + (uint32_t)(((buf * 128 + row) * LDA + c4) * 4),
                 X + (size_t)gr * K_TOTAL + k0 + c4);
        }
    };
    auto issueB = [&](int s) {
        const int k0 = s * BK;
        constexpr int BCH = BN * 8 / 256;
#pragma unroll
        for (int i = 0; i < BCH; i++) {
            int idx = t + i * 256;
            int row = idx >> 3, q = (idx & 7) * 8;
            cp16(bh_u + (uint32_t)((row * LDK + q) * 2),
                 Wt_hi + (size_t)row * K_TOTAL + k0 + q);
            cp16(bl_u + (uint32_t)((row * LDK + q) * 2),
                 Wt_lo + (size_t)row * K_TOTAL + k0 + q);
        }
    };

    float acc[2][BN / 16][4];
#pragma unroll
    for (int mt = 0; mt < 2; mt++)
#pragma unroll
        for (int nt = 0; nt < NT; nt++)
#pragma unroll
            for (int i = 0; i < 4; i++) acc[mt][nt][i] = 0.f;

    issueB(0); CP_COMMIT();
    issueA(0); CP_COMMIT();
    if (NITER > 1) { issueA(1); CP_COMMIT(); CP_WAIT(1); }
    else           { CP_WAIT(0); }
    __syncthreads();

    for (int c = 0; c < NITER; c++) {
        const int buf = c & 1;
#pragma unroll
        for (int ks = 0; ks < 4; ks++) {
            const int k = ks * 16;
            uint32_t ah[2][4], al[2][4];
#pragma unroll
            for (int mt = 0; mt < 2; mt++) {
                const int rb = buf * 128 + warp_m * 32 + mt * 16 + gq;
                const float* p0 = &Af[rb * LDA + k + gc2];
                float2 v0 = *(const float2*)(p0);
                float2 v1 = *(const float2*)(p0 + 8 * LDA);
                float2 v2 = *(const float2*)(p0 + 8);
                float2 v3 = *(const float2*)(p0 + 8 * LDA + 8);
                ah[mt][0] = split2(v0, al[mt][0]);
                ah[mt][1] = split2(v1, al[mt][1]);
                ah[mt][2] = split2(v2, al[mt][2]);
                ah[mt][3] = split2(v3, al[mt][3]);
            }
#pragma unroll
            for (int nt = 0; nt < NT; nt++) {
                const int nrow = n0 + nt * 8 + gq;
                const __nv_bfloat16* ph = &Bh[nrow * LDK + k + gc2];
                const __nv_bfloat16* pl = &Bl[nrow * LDK + k + gc2];
                uint32_t bh[2], bl[2];
                bh[0] = *(const uint32_t*)(ph);
                bh[1] = *(const uint32_t*)(ph + 8);
                bl[0] = *(const uint32_t*)(pl);
                bl[1] = *(const uint32_t*)(pl + 8);
#pragma unroll
                for (int mt = 0; mt < 2; mt++) {
                    mma_bf16(acc[mt][nt], ah[mt], bh);
                    mma_bf16(acc[mt][nt], ah[mt], bl);
                    mma_bf16(acc[mt][nt], al[mt], bh);
                }
            }
        }
        __syncthreads();
        if (c + 1 < NITER) {
            issueB(c + 1); CP_COMMIT();
            if (c + 2 < NITER) { issueA(c + 2); CP_COMMIT(); CP_WAIT(1); }
            else               { CP_WAIT(0); }
            __syncthreads();
        }
    }

#pragma unroll
    for (int nt = 0; nt < NT; nt++) {
        const int colb = n0 + nt * 8 + gc2;
        float2 bb = *(const float2*)&Bias[colb];
#pragma unroll
        for (int mt = 0; mt < 2; mt++) {
            int r0 = row0 + warp_m * 32 + mt * 16 + gq;
            if (r0 < row_limit) {
                float2 o0;
                o0.x = acc[mt][nt][0] + bb.x;
                o0.y = acc[mt][nt][1] + bb.y;
                *(float2*)&O[(size_t)r0 * BN + colb] = o0;
            }
            int r1 = r0 + 8;
            if (r1 < row_limit) {
                float2 o1;
                o1.x = acc[mt][nt][2] + bb.x;
                o1.y = acc[mt][nt][3] + bb.y;
                *(float2*)&O[(size_t)r1 * BN + colb] = o1;
            }
        }
    }
}

// ---------------- Segmented SpMM (edges pre-sorted lo|hi per row) -----------
template <bool FINAL>
__global__ __launch_bounds__(256) void spmm1_seg_kernel(
    const float* __restrict__ h1, float* __restrict__ h2) {
    int node = blockIdx.x * 8 + (threadIdx.x >> 5);
    int lane = threadIdx.x & 31;
    int s, e;
    if (FINAL) { s = g_mid[node]; e = g_rowptr[node + 1]; }
    else       { s = g_rowptr[node]; e = g_mid[node]; }

    float4 a0 = make_float4(0.f, 0.f, 0.f, 0.f);
    float4 a1 = a0, a2 = a0, a3 = a0;
    const float4* H = (const float4*)h1;

    int j = s;
    for (; j + 3 < e; j += 4) {
        int2 e0 = g_edge[j],     e1 = g_edge[j + 1];
        int2 e2 = g_edge[j + 2], e3 = g_edge[j + 3];
        float v0 = __int_as_float(e0.y), v1 = __int_as_float(e1.y);
        float v2 = __int_as_float(e2.y), v3 = __int_as_float(e3.y);
        float4 x0 = H[(size_t)e0.x * 32 + lane];
        float4 x1 = H[(size_t)e1.x * 32 + lane];
        float4 x2 = H[(size_t)e2.x * 32 + lane];
        float4 x3 = H[(size_t)e3.x * 32 + lane];
        a0.x += v0 * x0.x; a0.y += v0 * x0.y; a0.z += v0 * x0.z; a0.w += v0 * x0.w;
        a1.x += v1 * x1.x; a1.y += v1 * x1.y; a1.z += v1 * x1.z; a1.w += v1 * x1.w;
        a2.x += v2 * x2.x; a2.y += v2 * x2.y; a2.z += v2 * x2.z; a2.w += v2 * x2.w;
        a3.x += v3 * x3.x; a3.y += v3 * x3.y; a3.z += v3 * x3.z; a3.w += v3 * x3.w;
    }
    for (; j < e; j++) {
        int2 ed = g_edge[j];
        float v = __int_as_float(ed.y);
        float4 x = H[(size_t)ed.x * 32 + lane];
        a0.x += v * x.x; a0.y += v * x.y; a0.z += v * x.z; a0.w += v * x.w;
    }
    float4 o;
    o.x = a0.x + a1.x + a2.x + a3.x;
    o.y = a0.y + a1.y + a2.y + a3.y;
    o.z = a0.z + a1.z + a2.z + a3.z;
    o.w = a0.w + a1.w + a2.w + a3.w;
    if (FINAL) {
        float4 prev = ((const float4*)h2)[(size_t)node * 32 + lane];
        o.x = fmaxf(o.x + prev.x, 0.f);
        o.y = fmaxf(o.y + prev.y, 0.f);
        o.z = fmaxf(o.z + prev.z, 0.f);
        o.w = fmaxf(o.w + prev.w, 0.f);
    }
    ((float4*)h2)[(size_t)node * 32 + lane] = o;
}

template <bool FINAL>
__global__ __launch_bounds__(256) void spmm2_seg_kernel(
    const float* __restrict__ h3, float* __restrict__ out) {
    int node = blockIdx.x * 8 + (threadIdx.x >> 5);
    int lane = threadIdx.x & 31;
    int s, e;
    if (FINAL) { s = g_mid[node]; e = g_rowptr[node + 1]; }
    else       { s = g_rowptr[node]; e = g_mid[node]; }

    float2 a0 = make_float2(0.f, 0.f);
    float2 a1 = a0, a2 = a0, a3 = a0;
    const float2* H = (const float2*)h3;

    int j = s;
    for (; j + 3 < e; j += 4) {
        int2 e0 = g_edge[j],     e1 = g_edge[j + 1];
        int2 e2 = g_edge[j + 2], e3 = g_edge[j + 3];
        float v0 = __int_as_float(e0.y), v1 = __int_as_float(e1.y);
        float v2 = __int_as_float(e2.y), v3 = __int_as_float(e3.y);
        float2 x0 = H[(size_t)e0.x * 32 + lane];
        float2 x1 = H[(size_t)e1.x * 32 + lane];
        float2 x2 = H[(size_t)e2.x * 32 + lane];
        float2 x3 = H[(size_t)e3.x * 32 + lane];
        a0.x += v0 * x0.x; a0.y += v0 * x0.y;
        a1.x += v1 * x1.x; a1.y += v1 * x1.y;
        a2.x += v2 * x2.x; a2.y += v2 * x2.y;
        a3.x += v3 * x3.x; a3.y += v3 * x3.y;
    }
    for (; j < e; j++) {
        int2 ed = g_edge[j];
        float v = __int_as_float(ed.y);
        float2 x = H[(size_t)ed.x * 32 + lane];
        a0.x += v * x.x; a0.y += v * x.y;
    }
    float2 o;
    o.x = a0.x + a1.x + a2.x + a3.x;
    o.y = a0.y + a1.y + a2.y + a3.y;
    if (FINAL) {
        float2 prev = ((const float2*)out)[(size_t)node * 32 + lane];
        o.x += prev.x;
        o.y += prev.y;
    }
    ((float2*)out)[(size_t)node * 32 + lane] = o;
}

// ---------------- launch ----------------
#define SMEM_PIPE(BN) (2 * 128 * LDA * 4 + 2 * (BN) * LDK * 2)

extern "C" void kernel_launch(void* const* d_in, const int* in_sizes, int n_in,
                              void* d_out, int out_size) {
    const float* x       = (const float*)d_in[0];
    const int*   adj_row = (const int*)d_in[1];
    const int*   adj_col = (const int*)d_in[2];
    const float* adj_val = (const float*)d_in[3];
    const float* w1      = (const float*)d_in[4];
    const float* b1      = (const float*)d_in[5];
    const float* w2      = (const float*)d_in[6];
    const float* b2      = (const float*)d_in[7];
    float* out = (float*)d_out;

    float* h1 = nullptr; float* h2 = nullptr; float* h3 = nullptr;
    const __nv_bfloat16 *w1h, *w1l, *w2h, *w2l;
    cudaGetSymbolAddress((void**)&h1, g_h1);
    cudaGetSymbolAddress((void**)&h2, g_h2);
    cudaGetSymbolAddress((void**)&h3, g_h3);
    cudaGetSymbolAddress((void**)&w1h, g_w1t_hi);
    cudaGetSymbolAddress((void**)&w1l, g_w1t_lo);
    cudaGetSymbolAddress((void**)&w2h, g_w2t_hi);
    cudaGetSymbolAddress((void**)&w2l, g_w2t_lo);

    static cudaStream_t s1 = nullptr;
    static cudaEvent_t ev_fork, ev_g1h0, ev_p0, ev_g2h0, ev_sp20;
    static bool init_done = false;
    if (!init_done) {
        cudaFuncSetAttribute(gemm_pipe_kernel<HID_F, IN_F>,
                             cudaFuncAttributeMaxDynamicSharedMemorySize, SMEM_PIPE(HID_F));
        cudaFuncSetAttribute(gemm_pipe_kernel<N_CLS, HID_F>,
                             cudaFuncAttributeMaxDynamicSharedMemorySize, SMEM_PIPE(N_CLS));
        cudaStreamCreateWithFlags(&s1, cudaStreamNonBlocking);
        cudaEventCreateWithFlags(&ev_fork,  cudaEventDisableTiming);
        cudaEventCreateWithFlags(&ev_g1h0,  cudaEventDisableTiming);
        cudaEventCreateWithFlags(&ev_p0,    cudaEventDisableTiming);
        cudaEventCreateWithFlags(&ev_g2h0,  cudaEventDisableTiming);
        cudaEventCreateWithFlags(&ev_sp20,  cudaEventDisableTiming);
        init_done = true;
    }

    const int NBLK = N_NODES / 8;   // 12500

    // ---- side: segmented CSR build (overlaps prep + gemm1_h0) ----
    cudaEventRecord(ev_fork, 0);
    cudaStreamWaitEvent(s1, ev_fork, 0);
    zero_deg_kernel<<<(N_NODES + 256) / 256, 256, 0, s1>>>();
    count_kernel<<<(N_EDGES + 255) / 256, 256, 0, s1>>>(adj_row, adj_col);
    scan_kernel<<<1, 1024, 0, s1>>>();
    scatter_kernel<<<(N_EDGES + 255) / 256, 256, 0, s1>>>(adj_row, adj_col, adj_val);

    // ---- main: weight prep + gemm1 halves ----
    prep_w1t_kernel<<<(IN_F * HID_F + 255) / 256, 256>>>(w1);
    prep_w2t_kernel<<<(HID_F * N_CLS + 255) / 256, 256>>>(w2);
    gemm_pipe_kernel<HID_F, IN_F>
        <<<HALFN / 128, 256, SMEM_PIPE(HID_F)>>>(x, w1h, w1l, b1, h1, 0, HALFN);
    cudaEventRecord(ev_g1h0, 0);
    gemm_pipe_kernel<HID_F, IN_F>
        <<<(N_NODES - HALFN + 127) / 128, 256, SMEM_PIPE(HID_F)>>>(
            x, w1h, w1l, b1, h1, HALFN, N_NODES);

    // ---- side: spmm1 pass0 (lo cols; needs CSR [in-order] + h1 rows<HALFN)
    //      overlaps gemm1_h1 on main
    cudaStreamWaitEvent(s1, ev_g1h0, 0);
    spmm1_seg_kernel<false><<<NBLK, 256, 0, s1>>>(h1, h2);
    cudaEventRecord(ev_p0, s1);

    // ---- main: join, spmm1 pass1 (+ReLU), then gemm2 halves ----
    cudaStreamWaitEvent(0, ev_p0, 0);
    spmm1_seg_kernel<true><<<NBLK, 256>>>(h1, h2);
    gemm_pipe_kernel<N_CLS, HID_F>
        <<<HALFN / 128, 256, SMEM_PIPE(N_CLS)>>>(h2, w2h, w2l, b2, h3, 0, HALFN);
    cudaEventRecord(ev_g2h0, 0);
    gemm_pipe_kernel<N_CLS, HID_F>
        <<<(N_NODES - HALFN + 127) / 128, 256, SMEM_PIPE(N_CLS)>>>(
            h2, w2h, w2l, b2, h3, HALFN, N_NODES);

    // ---- side: spmm2 pass0 (lo cols; needs h3 rows<HALFN) ∥ gemm2_h1 ----
    cudaStreamWaitEvent(s1, ev_g2h0, 0);
    spmm2_seg_kernel<false><<<NBLK, 256, 0, s1>>>(h3, out);
    cudaEventRecord(ev_sp20, s1);

    // ---- main: join, spmm2 pass1 finalizes ----
    cudaStreamWaitEvent(0, ev_sp20, 0);
    spmm2_seg_kernel<true><<<NBLK, 256>>>(h3, out);
}

// round 12
// speedup vs baseline: 1.4412x; 1.4206x over previous
#include <cuda_runtime.h>
#include <cuda_bf16.h>
#include <cstdint>

#define N_NODES 100000
#define N_EDGES 1600000
#define IN_F    512
#define HID_F   128
#define N_CLS   64

// ---------------- device scratch (no allocations allowed) ----------------
__device__ __align__(16) float g_h1[(size_t)N_NODES * HID_F];
__device__ __align__(16) float g_h3[(size_t)N_NODES * N_CLS];
__device__ int   g_deg[N_NODES + 1];
__device__ int   g_rowptr[N_NODES + 1];
__device__ int   g_fill[N_NODES];
__device__ int2  g_edge[N_EDGES];                 // {col, float_bits(val)}
__device__ __align__(16) __nv_bfloat16 g_w1t_hi[HID_F * IN_F];   // [128][512]
__device__ __align__(16) __nv_bfloat16 g_w1t_lo[HID_F * IN_F];

// ---------------- small helpers ----------------
__device__ __forceinline__ uint32_t smem_u32(const void* p) {
    uint32_t a;
    asm("{ .reg .u64 t; cvta.to.shared.u64 t, %1; cvt.u32.u64 %0, t; }" : "=r"(a) : "l"(p));
    return a;
}
__device__ __forceinline__ void cp16(uint32_t dst, const void* src) {
    asm volatile("cp.async.ca.shared.global [%0], [%1], 16;" :: "r"(dst), "l"(src));
}
#define CP_COMMIT() asm volatile("cp.async.commit_group;" ::: "memory")
#define CP_WAIT(n)  asm volatile("cp.async.wait_group %0;" :: "n"(n) : "memory")

__device__ __forceinline__ void mma_bf16(float* c, const uint32_t* a, const uint32_t* b) {
    asm volatile(
        "mma.sync.aligned.m16n8k16.row.col.f32.bf16.bf16.f32 "
        "{%0,%1,%2,%3}, {%4,%5,%6,%7}, {%8,%9}, {%0,%1,%2,%3};"
        : "+f"(c[0]), "+f"(c[1]), "+f"(c[2]), "+f"(c[3])
        : "r"(a[0]), "r"(a[1]), "r"(a[2]), "r"(a[3]), "r"(b[0]), "r"(b[1]));
}
__device__ __forceinline__ uint32_t pack_bf16x2(__nv_bfloat16 a, __nv_bfloat16 b) {
    __nv_bfloat162 p; p.x = a; p.y = b;
    return *reinterpret_cast<uint32_t*>(&p);
}
__device__ __forceinline__ uint32_t split2(float2 v, uint32_t& lo) {
    __nv_bfloat16 h0 = __float2bfloat16(v.x), h1 = __float2bfloat16(v.y);
    lo = pack_bf16x2(__float2bfloat16(v.x - __bfloat162float(h0)),
                     __float2bfloat16(v.y - __bfloat162float(h1)));
    return pack_bf16x2(h0, h1);
}

// ---------------- CSR build (plain, R7-proven) ----------------
__global__ void zero_deg_kernel() {
    int i = blockIdx.x * blockDim.x + threadIdx.x;
    if (i <= N_NODES) g_deg[i] = 0;
}
__global__ void count_kernel(const int* __restrict__ row) {
    int e = blockIdx.x * blockDim.x + threadIdx.x;
    if (e < N_EDGES) atomicAdd(&g_deg[row[e]], 1);
}
__global__ __launch_bounds__(1024) void scan_kernel() {
    __shared__ int wsum[32];
    int t = threadIdx.x;
    const int CH = (N_NODES + 1023) / 1024;  // 98
    int base = t * CH;
    int s = 0;
#pragma unroll 4
    for (int j = 0; j < CH; j++) {
        int i = base + j;
        if (i < N_NODES) s += g_deg[i];
    }
    int lane = t & 31, wid = t >> 5;
    int v = s;
#pragma unroll
    for (int d = 1; d < 32; d <<= 1) {
        int n = __shfl_up_sync(0xFFFFFFFF, v, d);
        if (lane >= d) v += n;
    }
    if (lane == 31) wsum[wid] = v;
    __syncthreads();
    if (wid == 0) {
        int w = wsum[lane];
#pragma unroll
        for (int d = 1; d < 32; d <<= 1) {
            int n = __shfl_up_sync(0xFFFFFFFF, w, d);
            if (lane >= d) w += n;
        }
        wsum[lane] = w;
    }
    __syncthreads();
    int run = v - s + (wid ? wsum[wid - 1] : 0);
    for (int j = 0; j < CH; j++) {
        int i = base + j;
        if (i < N_NODES) {
            int d = g_deg[i];
            g_rowptr[i] = run;
            g_fill[i]   = run;
            run += d;
        }
    }
    if (t == 1023) g_rowptr[N_NODES] = N_EDGES;
}
__global__ void scatter_kernel(const int* __restrict__ row, const int* __restrict__ col,
                               const float* __restrict__ val) {
    int e = blockIdx.x * blockDim.x + threadIdx.x;
    if (e < N_EDGES) {
        int r = row[e];
        int p = atomicAdd(&g_fill[r], 1);
        g_edge[p] = make_int2(col[e], __float_as_int(val[e]));
    }
}

// ---------------- weight prep: w1 transpose + bf16 hi/lo split --------------
__global__ void prep_w1t_kernel(const float* __restrict__ w1) {
    int idx = blockIdx.x * blockDim.x + threadIdx.x;
    if (idx < IN_F * HID_F) {
        int k = idx >> 7, n = idx & 127;
        float v = w1[idx];
        __nv_bfloat16 h = __float2bfloat16(v);
        float r = v - __bfloat162float(h);
        g_w1t_hi[n * IN_F + k] = h;
        g_w1t_lo[n * IN_F + k] = __float2bfloat16(r);
    }
}

// ---------------- cp.async pipelined bf16-split GEMM1 (R7-proven) -----------
#define BK  64
#define LDK 72
#define LDA 68

template <int BN, int K_TOTAL>
__global__ __launch_bounds__(256) void gemm_pipe_kernel(
    const float* __restrict__ X,
    const __nv_bfloat16* __restrict__ Wt_hi,
    const __nv_bfloat16* __restrict__ Wt_lo,
    const float* __restrict__ Bias,
    float* __restrict__ O,
    int row_base, int row_limit) {
    constexpr int NITER = K_TOTAL / BK;
    extern __shared__ char smraw[];
    float* Af = (float*)smraw;                                   // [2][128][LDA]
    __nv_bfloat16* Bh = (__nv_bfloat16*)(Af + 2 * 128 * LDA);    // [BN][LDK]
    __nv_bfloat16* Bl = Bh + BN * LDK;

    const int t = threadIdx.x;
    const int lane = t & 31;
    const int wid = t >> 5;
    const int warp_m = wid & 3;
    const int warp_n = wid >> 2;
    const int NT = BN / 16;
    const int n0 = warp_n * (BN / 2);
    const int row0 = row_base + blockIdx.x * 128;
    const int gq = lane >> 2;
    const int gc2 = (lane & 3) * 2;

    const uint32_t af_u = smem_u32(Af);
    const uint32_t bh_u = smem_u32(Bh);
    const uint32_t bl_u = smem_u32(Bl);

    auto issueA = [&](int s) {
        const int buf = s & 1;
        const int k0 = s * BK;
#pragma unroll
        for (int i = 0; i < 8; i++) {
            int idx = t + i * 256;
            int row = idx >> 4, c4 = (idx & 15) * 4;
            int gr = row0 + row;
            if (gr >= N_NODES) gr = N_NODES - 1;
            cp16(af_u + (uint32_t)(((buf * 128 + row) * LDA + c4) * 4),
                 X + (size_t)gr * K_TOTAL + k0 + c4);
        }
    };
    auto issueB = [&](int s) {
        const int k0 = s * BK;
        constexpr int BCH = BN * 8 / 256;
#pragma unroll
        for (int i = 0; i < BCH; i++) {
            int idx = t + i * 256;
            int row = idx >> 3, q = (idx & 7) * 8;
            cp16(bh_u + (uint32_t)((row * LDK + q) * 2),
                 Wt_hi + (size_t)row * K_TOTAL + k0 + q);
            cp16(bl_u + (uint32_t)((row * LDK + q) * 2),
                 Wt_lo + (size_t)row * K_TOTAL + k0 + q);
        }
    };

    float acc[2][BN / 16][4];
#pragma unroll
    for (int mt = 0; mt < 2; mt++)
#pragma unroll
        for (int nt = 0; nt < NT; nt++)
#pragma unroll
            for (int i = 0; i < 4; i++) acc[mt][nt][i] = 0.f;

    issueB(0); CP_COMMIT();
    issueA(0); CP_COMMIT();
    if (NITER > 1) { issueA(1); CP_COMMIT(); CP_WAIT(1); }
    else           { CP_WAIT(0); }
    __syncthreads();

    for (int c = 0; c < NITER; c++) {
        const int buf = c & 1;
#pragma unroll
        for (int ks = 0; ks < 4; ks++) {
            const int k = ks * 16;
            uint32_t ah[2][4], al[2][4];
#pragma unroll
            for (int mt = 0; mt < 2; mt++) {
                const int rb = buf * 128 + warp_m * 32 + mt * 16 + gq;
                const float* p0 = &Af[rb * LDA + k + gc2];
                float2 v0 = *(const float2*)(p0);
                float2 v1 = *(const float2*)(p0 + 8 * LDA);
                float2 v2 = *(const float2*)(p0 + 8);
                float2 v3 = *(const float2*)(p0 + 8 * LDA + 8);
                ah[mt][0] = split2(v0, al[mt][0]);
                ah[mt][1] = split2(v1, al[mt][1]);
                ah[mt][2] = split2(v2, al[mt][2]);
                ah[mt][3] = split2(v3, al[mt][3]);
            }
#pragma unroll
            for (int nt = 0; nt < NT; nt++) {
                const int nrow = n0 + nt * 8 + gq;
                const __nv_bfloat16* ph = &Bh[nrow * LDK + k + gc2];
                const __nv_bfloat16* pl = &Bl[nrow * LDK + k + gc2];
                uint32_t bh[2], bl[2];
                bh[0] = *(const uint32_t*)(ph);
                bh[1] = *(const uint32_t*)(ph + 8);
                bl[0] = *(const uint32_t*)(pl);
                bl[1] = *(const uint32_t*)(pl + 8);
#pragma unroll
                for (int mt = 0; mt < 2; mt++) {
                    mma_bf16(acc[mt][nt], ah[mt], bh);
                    mma_bf16(acc[mt][nt], ah[mt], bl);
                    mma_bf16(acc[mt][nt], al[mt], bh);
                }
            }
        }
        __syncthreads();
        if (c + 1 < NITER) {
            issueB(c + 1); CP_COMMIT();
            if (c + 2 < NITER) { issueA(c + 2); CP_COMMIT(); CP_WAIT(1); }
            else               { CP_WAIT(0); }
            __syncthreads();
        }
    }

#pragma unroll
    for (int nt = 0; nt < NT; nt++) {
        const int colb = n0 + nt * 8 + gc2;
        float2 bb = *(const float2*)&Bias[colb];
#pragma unroll
        for (int mt = 0; mt < 2; mt++) {
            int r0 = row0 + warp_m * 32 + mt * 16 + gq;
            if (r0 < row_limit) {
                float2 o0;
                o0.x = acc[mt][nt][0] + bb.x;
                o0.y = acc[mt][nt][1] + bb.y;
                *(float2*)&O[(size_t)r0 * BN + colb] = o0;
            }
            int r1 = r0 + 8;
            if (r1 < row_limit) {
                float2 o1;
                o1.x = acc[mt][nt][2] + bb.x;
                o1.y = acc[mt][nt][3] + bb.y;
                *(float2*)&O[(size_t)r1 * BN + colb] = o1;
            }
        }
    }
}

// ---------------- Fused spmm1 + gemm2: h3 = relu(A@h1)·W2 + b2 --------------
// Block = 8 nodes (warp-per-node gather), then in-block fp32 mini-GEMM.
// W2 (32 KB) prefetched via cp.async during the gather; FMA overlaps
// gathers of concurrent blocks on the same SM.
__global__ __launch_bounds__(256) void spmm1_gemm2_fused_kernel(
    const float* __restrict__ h1, const float* __restrict__ w2,
    const float* __restrict__ b2, float* __restrict__ h3) {
    __shared__ float W2s[HID_F * N_CLS];     // 32 KB, [k][c] layout (c stride 1)
    __shared__ float b2s[N_CLS];
    __shared__ float h2s[8 * HID_F];         // 4 KB

    int t = threadIdx.x, wid = t >> 5, lane = t & 31;

    // prefetch W2 + b2 (overlaps gather)
    {
        uint32_t w2u = smem_u32(W2s);
#pragma unroll
        for (int i = 0; i < 8; i++)
            cp16(w2u + (uint32_t)((t + i * 256) * 16), w2 + (size_t)(t + i * 256) * 4);
        if (t < 16) cp16(smem_u32(b2s) + t * 16, b2 + t * 4);
        CP_COMMIT();
    }

    // ---- gather: node = 8*blockIdx + wid, lane owns 4 features ----
    int node = blockIdx.x * 8 + wid;
    int s = g_rowptr[node], e = g_rowptr[node + 1];
    float4 a0 = make_float4(0.f, 0.f, 0.f, 0.f);
    float4 a1 = a0, a2 = a0, a3 = a0;
    const float4* H = (const float4*)h1;
    int j = s;
    for (; j + 3 < e; j += 4) {
        int2 e0 = g_edge[j],     e1 = g_edge[j + 1];
        int2 e2 = g_edge[j + 2], e3 = g_edge[j + 3];
        float v0 = __int_as_float(e0.y), v1 = __int_as_float(e1.y);
        float v2 = __int_as_float(e2.y), v3 = __int_as_float(e3.y);
        float4 x0 = H[(size_t)e0.x * 32 + lane];
        float4 x1 = H[(size_t)e1.x * 32 + lane];
        float4 x2 = H[(size_t)e2.x * 32 + lane];
        float4 x3 = H[(size_t)e3.x * 32 + lane];
        a0.x += v0 * x0.x; a0.y += v0 * x0.y; a0.z += v0 * x0.z; a0.w += v0 * x0.w;
        a1.x += v1 * x1.x; a1.y += v1 * x1.y; a1.z += v1 * x1.z; a1.w += v1 * x1.w;
        a2.x += v2 * x2.x; a2.y += v2 * x2.y; a2.z += v2 * x2.z; a2.w += v2 * x2.w;
        a3.x += v3 * x3.x; a3.y += v3 * x3.y; a3.z += v3 * x3.z; a3.w += v3 * x3.w;
    }
    for (; j < e; j++) {
        int2 ed = g_edge[j];
        float v = __int_as_float(ed.y);
        float4 x = H[(size_t)ed.x * 32 + lane];
        a0.x += v * x.x; a0.y += v * x.y; a0.z += v * x.z; a0.w += v * x.w;
    }
    float4 o;
    o.x = fmaxf(a0.x + a1.x + a2.x + a3.x, 0.f);
    o.y = fmaxf(a0.y + a1.y + a2.y + a3.y, 0.f);
    o.z = fmaxf(a0.z + a1.z + a2.z + a3.z, 0.f);
    o.w = fmaxf(a0.w + a1.w + a2.w + a3.w, 0.f);
    *(float4*)&h2s[wid * HID_F + lane * 4] = o;

    CP_WAIT(0);
    __syncthreads();

    // ---- mini-GEMM: out[8 x 64] = h2s[8 x 128] @ W2s[128 x 64] + b2 ----
    // thread handles (n1 = t>>6, c) and (n2 = n1+4, c): shared W2s reads.
    {
        int c  = t & 63;
        int n1 = t >> 6;          // 0..3
        int n2 = n1 + 4;          // 4..7
        const float* r1 = &h2s[n1 * HID_F];
        const float* r2 = &h2s[n2 * HID_F];
        float acc1 = b2s[c], acc2 = b2s[c];
#pragma unroll 16
        for (int k = 0; k < HID_F; k++) {
            float w = W2s[k * N_CLS + c];
            acc1 += r1[k] * w;
            acc2 += r2[k] * w;
        }
        size_t base = (size_t)blockIdx.x * 8;
        h3[(base + n1) * N_CLS + c] = acc1;
        h3[(base + n2) * N_CLS + c] = acc2;
    }
}

// ---------------- SpMM2: warp-per-node, 4-edge unroll (R7-proven) -----------
__global__ __launch_bounds__(256) void spmm2_warp_kernel(
    const float* __restrict__ h3, float* __restrict__ out) {
    int node = blockIdx.x * 8 + (threadIdx.x >> 5);
    int lane = threadIdx.x & 31;
    int s = g_rowptr[node], e = g_rowptr[node + 1];

    float2 a0 = make_float2(0.f, 0.f);
    float2 a1 = a0, a2 = a0, a3 = a0;
    const float2* H = (const float2*)h3;

    int j = s;
    for (; j + 3 < e; j += 4) {
        int2 e0 = g_edge[j],     e1 = g_edge[j + 1];
        int2 e2 = g_edge[j + 2], e3 = g_edge[j + 3];
        float v0 = __int_as_float(e0.y), v1 = __int_as_float(e1.y);
        float v2 = __int_as_float(e2.y), v3 = __int_as_float(e3.y);
        float2 x0 = H[(size_t)e0.x * 32 + lane];
        float2 x1 = H[(size_t)e1.x * 32 + lane];
        float2 x2 = H[(size_t)e2.x * 32 + lane];
        float2 x3 = H[(size_t)e3.x * 32 + lane];
        a0.x += v0 * x0.x; a0.y += v0 * x0.y;
        a1.x += v1 * x1.x; a1.y += v1 * x1.y;
        a2.x += v2 * x2.x; a2.y += v2 * x2.y;
        a3.x += v3 * x3.x; a3.y += v3 * x3.y;
    }
    for (; j < e; j++) {
        int2 ed = g_edge[j];
        float v = __int_as_float(ed.y);
        float2 x = H[(size_t)ed.x * 32 + lane];
        a0.x += v * x.x; a0.y += v * x.y;
    }
    float2 o;
    o.x = a0.x + a1.x + a2.x + a3.x;
    o.y = a0.y + a1.y + a2.y + a3.y;
    ((float2*)out)[(size_t)node * 32 + lane] = o;
}

// ---------------- launch ----------------
#define SMEM_PIPE(BN) (2 * 128 * LDA * 4 + 2 * (BN) * LDK * 2)

extern "C" void kernel_launch(void* const* d_in, const int* in_sizes, int n_in,
                              void* d_out, int out_size) {
    const float* x       = (const float*)d_in[0];
    const int*   adj_row = (const int*)d_in[1];
    const int*   adj_col = (const int*)d_in[2];
    const float* adj_val = (const float*)d_in[3];
    const float* w1      = (const float*)d_in[4];
    const float* b1      = (const float*)d_in[5];
    const float* w2      = (const float*)d_in[6];
    const float* b2      = (const float*)d_in[7];
    float* out = (float*)d_out;

    float* h1 = nullptr; float* h3 = nullptr;
    const __nv_bfloat16 *w1h, *w1l;
    cudaGetSymbolAddress((void**)&h1, g_h1);
    cudaGetSymbolAddress((void**)&h3, g_h3);
    cudaGetSymbolAddress((void**)&w1h, g_w1t_hi);
    cudaGetSymbolAddress((void**)&w1l, g_w1t_lo);

    static cudaStream_t s1 = nullptr;
    static cudaEvent_t ev_fork, ev_join;
    static bool init_done = false;
    if (!init_done) {
        cudaFuncSetAttribute(gemm_pipe_kernel<HID_F, IN_F>,
                             cudaFuncAttributeMaxDynamicSharedMemorySize, SMEM_PIPE(HID_F));
        cudaStreamCreateWithFlags(&s1, cudaStreamNonBlocking);
        cudaEventCreateWithFlags(&ev_fork, cudaEventDisableTiming);
        cudaEventCreateWithFlags(&ev_join, cudaEventDisableTiming);
        init_done = true;
    }

    const int NBLK = N_NODES / 8;   // 12500

    // ---- side: CSR build (overlaps prep + gemm1) ----
    cudaEventRecord(ev_fork, 0);
    cudaStreamWaitEvent(s1, ev_fork, 0);
    zero_deg_kernel<<<(N_NODES + 256) / 256, 256, 0, s1>>>();
    count_kernel<<<(N_EDGES + 255) / 256, 256, 0, s1>>>(adj_row);
    scan_kernel<<<1, 1024, 0, s1>>>();
    scatter_kernel<<<(N_EDGES + 255) / 256, 256, 0, s1>>>(adj_row, adj_col, adj_val);
    cudaEventRecord(ev_join, s1);

    // ---- main: weight prep + gemm1 (full) ----
    prep_w1t_kernel<<<(IN_F * HID_F + 255) / 256, 256>>>(w1);
    gemm_pipe_kernel<HID_F, IN_F>
        <<<(N_NODES + 127) / 128, 256, SMEM_PIPE(HID_F)>>>(x, w1h, w1l, b1, h1, 0, N_NODES);

    // ---- join: fused spmm1+gemm2, then spmm2 ----
    cudaStreamWaitEvent(0, ev_join, 0);
    spmm1_gemm2_fused_kernel<<<NBLK, 256>>>(h1, w2, b2, h3);
    spmm2_warp_kernel<<<NBLK, 256>>>(h3, out);
}

// round 13
// speedup vs baseline: 1.6870x; 1.1706x over previous
#include <cuda_runtime.h>
#include <cuda_bf16.h>
#include <cstdint>

#define N_NODES 100000
#define N_EDGES 1600000
#define IN_F    512
#define HID_F   128
#define N_CLS   64
#define HALF_N  50048            // split point, multiple of 128 and 8

// ---------------- device scratch (no allocations allowed) ----------------
__device__ __align__(16) float g_h1[(size_t)N_NODES * HID_F];
__device__ __align__(16) float g_h2[(size_t)N_NODES * HID_F];
__device__ __align__(16) float g_h3[(size_t)N_NODES * N_CLS];
__device__ int   g_deg[N_NODES + 1];
__device__ int   g_rowptr[N_NODES + 1];
__device__ int   g_fill[N_NODES];
__device__ int2  g_edge[N_EDGES];                 // {col, float_bits(val)}
__device__ __align__(16) __nv_bfloat16 g_w1t_hi[HID_F * IN_F];   // [128][512]
__device__ __align__(16) __nv_bfloat16 g_w1t_lo[HID_F * IN_F];
__device__ __align__(16) __nv_bfloat16 g_w2t_hi[N_CLS * HID_F];  // [64][128]
__device__ __align__(16) __nv_bfloat16 g_w2t_lo[N_CLS * HID_F];

// ---------------- small helpers ----------------
__device__ __forceinline__ uint32_t smem_u32(const void* p) {
    uint32_t a;
    asm("{ .reg .u64 t; cvta.to.shared.u64 t, %1; cvt.u32.u64 %0, t; }" : "=r"(a) : "l"(p));
    return a;
}
__device__ __forceinline__ void cp16(uint32_t dst, const void* src) {
    asm volatile("cp.async.ca.shared.global [%0], [%1], 16;" :: "r"(dst), "l"(src));
}
#define CP_COMMIT() asm volatile("cp.async.commit_group;" ::: "memory")
#define CP_WAIT(n)  asm volatile("cp.async.wait_group %0;" :: "n"(n) : "memory")

__device__ __forceinline__ void mma_bf16(float* c, const uint32_t* a, const uint32_t* b) {
    asm volatile(
        "mma.sync.aligned.m16n8k16.row.col.f32.bf16.bf16.f32 "
        "{%0,%1,%2,%3}, {%4,%5,%6,%7}, {%8,%9}, {%0,%1,%2,%3};"
        : "+f"(c[0]), "+f"(c[1]), "+f"(c[2]), "+f"(c[3])
        : "r"(a[0]), "r"(a[1]), "r"(a[2]), "r"(a[3]), "r"(b[0]), "r"(b[1]));
}
__device__ __forceinline__ uint32_t pack_bf16x2(__nv_bfloat16 a, __nv_bfloat16 b) {
    __nv_bfloat162 p; p.x = a; p.y = b;
    return *reinterpret_cast<uint32_t*>(&p);
}
// FAST split: hi = truncate-to-bf16 (exact top 16 bits), lo = rn(v - hi).
// 1 PRMT for the hi pair, 1 packed cvt for the lo pair, 2 AND + 2 FSUB.
__device__ __forceinline__ uint32_t split2(float2 v, uint32_t& lo) {
    uint32_t u0 = __float_as_uint(v.x);
    uint32_t u1 = __float_as_uint(v.y);
    float l0 = v.x - __uint_as_float(u0 & 0xFFFF0000u);
    float l1 = v.y - __uint_as_float(u1 & 0xFFFF0000u);
    uint32_t hi, lou;
    asm("prmt.b32 %0, %1, %2, 0x7632;" : "=r"(hi) : "r"(u0), "r"(u1));
    asm("cvt.rn.bf16x2.f32 %0, %1, %2;" : "=r"(lou) : "f"(l1), "f"(l0));
    lo = lou;
    return hi;
}

// ---------------- CSR build ----------------
__global__ void zero_deg_kernel() {
    int i = blockIdx.x * blockDim.x + threadIdx.x;
    if (i <= N_NODES) g_deg[i] = 0;
}
__global__ void count_kernel(const int* __restrict__ row) {
    int e = blockIdx.x * blockDim.x + threadIdx.x;
    if (e < N_EDGES) atomicAdd(&g_deg[row[e]], 1);
}
__global__ __launch_bounds__(1024) void scan_kernel() {
    __shared__ int wsum[32];
    int t = threadIdx.x;
    const int CH = (N_NODES + 1023) / 1024;  // 98
    int base = t * CH;
    int s = 0;
#pragma unroll 4
    for (int j = 0; j < CH; j++) {
        int i = base + j;
        if (i < N_NODES) s += g_deg[i];
    }
    int lane = t & 31, wid = t >> 5;
    int v = s;
#pragma unroll
    for (int d = 1; d < 32; d <<= 1) {
        int n = __shfl_up_sync(0xFFFFFFFF, v, d);
        if (lane >= d) v += n;
    }
    if (lane == 31) wsum[wid] = v;
    __syncthreads();
    if (wid == 0) {
        int w = wsum[lane];
#pragma unroll
        for (int d = 1; d < 32; d <<= 1) {
            int n = __shfl_up_sync(0xFFFFFFFF, w, d);
            if (lane >= d) w += n;
        }
        wsum[lane] = w;
    }
    __syncthreads();
    int run = v - s + (wid ? wsum[wid - 1] : 0);
    for (int j = 0; j < CH; j++) {
        int i = base + j;
        if (i < N_NODES) {
            int d = g_deg[i];
            g_rowptr[i] = run;
            g_fill[i]   = run;
            run += d;
        }
    }
    if (t == 1023) g_rowptr[N_NODES] = N_EDGES;
}
__global__ void scatter_kernel(const int* __restrict__ row, const int* __restrict__ col,
                               const float* __restrict__ val) {
    int e = blockIdx.x * blockDim.x + threadIdx.x;
    if (e < N_EDGES) {
        int r = row[e];
        int p = atomicAdd(&g_fill[r], 1);
        g_edge[p] = make_int2(col[e], __float_as_int(val[e]));
    }
}

// ---------------- weight prep: transpose + bf16 hi/lo split ----------------
__global__ void prep_w1t_kernel(const float* __restrict__ w1) {
    int idx = blockIdx.x * blockDim.x + threadIdx.x;
    if (idx < IN_F * HID_F) {
        int k = idx >> 7, n = idx & 127;
        float v = w1[idx];
        __nv_bfloat16 h = __float2bfloat16(v);
        float r = v - __bfloat162float(h);
        g_w1t_hi[n * IN_F + k] = h;
        g_w1t_lo[n * IN_F + k] = __float2bfloat16(r);
    }
}
__global__ void prep_w2t_kernel(const float* __restrict__ w2) {
    int idx = blockIdx.x * blockDim.x + threadIdx.x;
    if (idx < HID_F * N_CLS) {
        int k = idx >> 6, n = idx & 63;
        float v = w2[idx];
        __nv_bfloat16 h = __float2bfloat16(v);
        float r = v - __bfloat162float(h);
        g_w2t_hi[n * HID_F + k] = h;
        g_w2t_lo[n * HID_F + k] = __float2bfloat16(r);
    }
}

// ---------------- cp.async pipelined bf16-split GEMM (R7-proven) ------------
// CTA tile 128 x BN; 4 M-warps x 2 N-warps.
// A: fp32, 2-deep cp.async ring. B: pre-split bf16 weights, single buffer.
#define BK  64
#define LDK 72
#define LDA 68

template <int BN, int K_TOTAL>
__global__ __launch_bounds__(256) void gemm_pipe_kernel(
    const float* __restrict__ X,
    const __nv_bfloat16* __restrict__ Wt_hi,
    const __nv_bfloat16* __restrict__ Wt_lo,
    const float* __restrict__ Bias,
    float* __restrict__ O,
    int row_base, int row_limit) {
    constexpr int NITER = K_TOTAL / BK;
    extern __shared__ char smraw[];
    float* Af = (float*)smraw;                                   // [2][128][LDA]
    __nv_bfloat16* Bh = (__nv_bfloat16*)(Af + 2 * 128 * LDA);    // [BN][LDK]
    __nv_bfloat16* Bl = Bh + BN * LDK;

    const int t = threadIdx.x;
    const int lane = t & 31;
    const int wid = t >> 5;
    const int warp_m = wid & 3;
    const int warp_n = wid >> 2;
    const int NT = BN / 16;
    const int n0 = warp_n * (BN / 2);
    const int row0 = row_base + blockIdx.x * 128;
    const int gq = lane >> 2;
    const int gc2 = (lane & 3) * 2;

    const uint32_t af_u = smem_u32(Af);
    const uint32_t bh_u = smem_u32(Bh);
    const uint32_t bl_u = smem_u32(Bl);

    auto issueA = [&](int s) {
        const int buf = s & 1;
        const int k0 = s * BK;
#pragma unroll
        for (int i = 0; i < 8; i++) {
            int idx = t + i * 256;
            int row = idx >> 4, c4 = (idx & 15) * 4;
            int gr = row0 + row;
            if (gr >= N_NODES) gr = N_NODES - 1;
            cp16(af_u + (uint32_t)(((buf * 128 + row) * LDA + c4) * 4),
                 X + (size_t)gr * K_TOTAL + k0 + c4);
        }
    };
    auto issueB = [&](int s) {
        const int k0 = s * BK;
        constexpr int BCH = BN * 8 / 256;
#pragma unroll
        for (int i = 0; i < BCH; i++) {
            int idx = t + i * 256;
            int row = idx >> 3, q = (idx & 7) * 8;
            cp16(bh_u + (uint32_t)((row * LDK + q) * 2),
                 Wt_hi + (size_t)row * K_TOTAL + k0 + q);
            cp16(bl_u + (uint32_t)((row * LDK + q) * 2),
                 Wt_lo + (size_t)row * K_TOTAL + k0 + q);
        }
    };

    float acc[2][BN / 16][4];
#pragma unroll
    for (int mt = 0; mt < 2; mt++)
#pragma unroll
        for (int nt = 0; nt < NT; nt++)
#pragma unroll
            for (int i = 0; i < 4; i++) acc[mt][nt][i] = 0.f;

    issueB(0); CP_COMMIT();
    issueA(0); CP_COMMIT();
    if (NITER > 1) { issueA(1); CP_COMMIT(); CP_WAIT(1); }
    else           { CP_WAIT(0); }
    __syncthreads();

    for (int c = 0; c < NITER; c++) {
        const int buf = c & 1;
#pragma unroll
        for (int ks = 0; ks < 4; ks++) {
            const int k = ks * 16;
            uint32_t ah[2][4], al[2][4];
#pragma unroll
            for (int mt = 0; mt < 2; mt++) {
                const int rb = buf * 128 + warp_m * 32 + mt * 16 + gq;
                const float* p0 = &Af[rb * LDA + k + gc2];
                float2 v0 = *(const float2*)(p0);
                float2 v1 = *(const float2*)(p0 + 8 * LDA);
                float2 v2 = *(const float2*)(p0 + 8);
                float2 v3 = *(const float2*)(p0 + 8 * LDA + 8);
                ah[mt][0] = split2(v0, al[mt][0]);
                ah[mt][1] = split2(v1, al[mt][1]);
                ah[mt][2] = split2(v2, al[mt][2]);
                ah[mt][3] = split2(v3, al[mt][3]);
            }
#pragma unroll
            for (int nt = 0; nt < NT; nt++) {
                const int nrow = n0 + nt * 8 + gq;
                const __nv_bfloat16* ph = &Bh[nrow * LDK + k + gc2];
                const __nv_bfloat16* pl = &Bl[nrow * LDK + k + gc2];
                uint32_t bh[2], bl[2];
                bh[0] = *(const uint32_t*)(ph);
                bh[1] = *(const uint32_t*)(ph + 8);
                bl[0] = *(const uint32_t*)(pl);
                bl[1] = *(const uint32_t*)(pl + 8);
#pragma unroll
                for (int mt = 0; mt < 2; mt++) {
                    mma_bf16(acc[mt][nt], ah[mt], bh);
                    mma_bf16(acc[mt][nt], ah[mt], bl);
                    mma_bf16(acc[mt][nt], al[mt], bh);
                }
            }
        }
        __syncthreads();
        if (c + 1 < NITER) {
            issueB(c + 1); CP_COMMIT();
            if (c + 2 < NITER) { issueA(c + 2); CP_COMMIT(); CP_WAIT(1); }
            else               { CP_WAIT(0); }
            __syncthreads();
        }
    }

#pragma unroll
    for (int nt = 0; nt < NT; nt++) {
        const int colb = n0 + nt * 8 + gc2;
        float2 bb = *(const float2*)&Bias[colb];
#pragma unroll
        for (int mt = 0; mt < 2; mt++) {
            int r0 = row0 + warp_m * 32 + mt * 16 + gq;
            if (r0 < row_limit) {
                float2 o0;
                o0.x = acc[mt][nt][0] + bb.x;
                o0.y = acc[mt][nt][1] + bb.y;
                *(float2*)&O[(size_t)r0 * BN + colb] = o0;
            }
            int r1 = r0 + 8;
            if (r1 < row_limit) {
                float2 o1;
                o1.x = acc[mt][nt][2] + bb.x;
                o1.y = acc[mt][nt][3] + bb.y;
                *(float2*)&O[(size_t)r1 * BN + colb] = o1;
            }
        }
    }
}

// ---------------- SpMM: warp-per-node, 4-edge unroll, no atomics ------------
__global__ __launch_bounds__(256) void spmm1_warp_kernel(
    const float* __restrict__ h1, float* __restrict__ h2, int node_base) {
    int node = node_base + blockIdx.x * 8 + (threadIdx.x >> 5);
    int lane = threadIdx.x & 31;
    int s = g_rowptr[node], e = g_rowptr[node + 1];

    float4 a0 = make_float4(0.f, 0.f, 0.f, 0.f);
    float4 a1 = a0, a2 = a0, a3 = a0;
    const float4* H = (const float4*)h1;

    int j = s;
    for (; j + 3 < e; j += 4) {
        int2 e0 = g_edge[j],     e1 = g_edge[j + 1];
        int2 e2 = g_edge[j + 2], e3 = g_edge[j + 3];
        float v0 = __int_as_float(e0.y), v1 = __int_as_float(e1.y);
        float v2 = __int_as_float(e2.y), v3 = __int_as_float(e3.y);
        float4 x0 = H[(size_t)e0.x * 32 + lane];
        float4 x1 = H[(size_t)e1.x * 32 + lane];
        float4 x2 = H[(size_t)e2.x * 32 + lane];
        float4 x3 = H[(size_t)e3.x * 32 + lane];
        a0.x += v0 * x0.x; a0.y += v0 * x0.y; a0.z += v0 * x0.z; a0.w += v0 * x0.w;
        a1.x += v1 * x1.x; a1.y += v1 * x1.y; a1.z += v1 * x1.z; a1.w += v1 * x1.w;
        a2.x += v2 * x2.x; a2.y += v2 * x2.y; a2.z += v2 * x2.z; a2.w += v2 * x2.w;
        a3.x += v3 * x3.x; a3.y += v3 * x3.y; a3.z += v3 * x3.z; a3.w += v3 * x3.w;
    }
    for (; j < e; j++) {
        int2 ed = g_edge[j];
        float v = __int_as_float(ed.y);
        float4 x = H[(size_t)ed.x * 32 + lane];
        a0.x += v * x.x; a0.y += v * x.y; a0.z += v * x.z; a0.w += v * x.w;
    }
    float4 o;
    o.x = fmaxf(a0.x + a1.x + a2.x + a3.x, 0.f);
    o.y = fmaxf(a0.y + a1.y + a2.y + a3.y, 0.f);
    o.z = fmaxf(a0.z + a1.z + a2.z + a3.z, 0.f);
    o.w = fmaxf(a0.w + a1.w + a2.w + a3.w, 0.f);
    ((float4*)h2)[(size_t)node * 32 + lane] = o;
}

__global__ __launch_bounds__(256) void spmm2_warp_kernel(
    const float* __restrict__ h3, float* __restrict__ out) {
    int node = blockIdx.x * 8 + (threadIdx.x >> 5);
    int lane = threadIdx.x & 31;
    int s = g_rowptr[node], e = g_rowptr[node + 1];

    float2 a0 = make_float2(0.f, 0.f);
    float2 a1 = a0, a2 = a0, a3 = a0;
    const float2* H = (const float2*)h3;

    int j = s;
    for (; j + 3 < e; j += 4) {
        int2 e0 = g_edge[j],     e1 = g_edge[j + 1];
        int2 e2 = g_edge[j + 2], e3 = g_edge[j + 3];
        float v0 = __int_as_float(e0.y), v1 = __int_as_float(e1.y);
        float v2 = __int_as_float(e2.y), v3 = __int_as_float(e3.y);
        float2 x0 = H[(size_t)e0.x * 32 + lane];
        float2 x1 = H[(size_t)e1.x * 32 + lane];
        float2 x2 = H[(size_t)e2.x * 32 + lane];
        float2 x3 = H[(size_t)e3.x * 32 + lane];
        a0.x += v0 * x0.x; a0.y += v0 * x0.y;
        a1.x += v1 * x1.x; a1.y += v1 * x1.y;
        a2.x += v2 * x2.x; a2.y += v2 * x2.y;
        a3.x += v3 * x3.x; a3.y += v3 * x3.y;
    }
    for (; j < e; j++) {
        int2 ed = g_edge[j];
        float v = __int_as_float(ed.y);
        float2 x = H[(size_t)ed.x * 32 + lane];
        a0.x += v * x.x; a0.y += v * x.y;
    }
    float2 o;
    o.x = a0.x + a1.x + a2.x + a3.x;
    o.y = a0.y + a1.y + a2.y + a3.y;
    ((float2*)out)[(size_t)node * 32 + lane] = o;
}

// ---------------- launch ----------------
#define SMEM_PIPE(BN) (2 * 128 * LDA * 4 + 2 * (BN) * LDK * 2)

extern "C" void kernel_launch(void* const* d_in, const int* in_sizes, int n_in,
                              void* d_out, int out_size) {
    const float* x       = (const float*)d_in[0];
    const int*   adj_row = (const int*)d_in[1];
    const int*   adj_col = (const int*)d_in[2];
    const float* adj_val = (const float*)d_in[3];
    const float* w1      = (const float*)d_in[4];
    const float* b1      = (const float*)d_in[5];
    const float* w2      = (const float*)d_in[6];
    const float* b2      = (const float*)d_in[7];
    float* out = (float*)d_out;

    float* h1 = nullptr; float* h2 = nullptr; float* h3 = nullptr;
    const __nv_bfloat16 *w1h, *w1l, *w2h, *w2l;
    cudaGetSymbolAddress((void**)&h1, g_h1);
    cudaGetSymbolAddress((void**)&h2, g_h2);
    cudaGetSymbolAddress((void**)&h3, g_h3);
    cudaGetSymbolAddress((void**)&w1h, g_w1t_hi);
    cudaGetSymbolAddress((void**)&w1l, g_w1t_lo);
    cudaGetSymbolAddress((void**)&w2h, g_w2t_hi);
    cudaGetSymbolAddress((void**)&w2l, g_w2t_lo);

    static cudaStream_t s_side = nullptr;
    static cudaEvent_t ev_fork, ev_join, ev_g1, ev_l2;
    static bool init_done = false;
    if (!init_done) {
        cudaFuncSetAttribute(gemm_pipe_kernel<HID_F, IN_F>,
                             cudaFuncAttributeMaxDynamicSharedMemorySize, SMEM_PIPE(HID_F));
        cudaFuncSetAttribute(gemm_pipe_kernel<N_CLS, HID_F>,
                             cudaFuncAttributeMaxDynamicSharedMemorySize, SMEM_PIPE(N_CLS));
        cudaStreamCreateWithFlags(&s_side, cudaStreamNonBlocking);
        cudaEventCreateWithFlags(&ev_fork, cudaEventDisableTiming);
        cudaEventCreateWithFlags(&ev_join, cudaEventDisableTiming);
        cudaEventCreateWithFlags(&ev_g1,   cudaEventDisableTiming);
        cudaEventCreateWithFlags(&ev_l2,   cudaEventDisableTiming);
        init_done = true;
    }

    // ---- fork: CSR build on side stream, concurrent with prep + gemm1 ----
    cudaEventRecord(ev_fork, 0);
    cudaStreamWaitEvent(s_side, ev_fork, 0);

    zero_deg_kernel<<<(N_NODES + 256) / 256, 256, 0, s_side>>>();
    count_kernel<<<(N_EDGES + 255) / 256, 256, 0, s_side>>>(adj_row);
    scan_kernel<<<1, 1024, 0, s_side>>>();
    scatter_kernel<<<(N_EDGES + 255) / 256, 256, 0, s_side>>>(adj_row, adj_col, adj_val);
    cudaEventRecord(ev_join, s_side);

    // ---- main stream: weight prep + gemm1 (all rows) ----
    prep_w1t_kernel<<<(IN_F * HID_F + 255) / 256, 256>>>(w1);
    prep_w2t_kernel<<<(HID_F * N_CLS + 255) / 256, 256>>>(w2);
    gemm_pipe_kernel<HID_F, IN_F>
        <<<(N_NODES + 127) / 128, 256, SMEM_PIPE(HID_F)>>>(x, w1h, w1l, b1, h1, 0, N_NODES);
    cudaEventRecord(ev_g1, 0);

    // ---- layer-1 aggregation + layer-2 projection, split in halves ----
    cudaStreamWaitEvent(0, ev_join, 0);
    spmm1_warp_kernel<<<HALF_N / 8, 256>>>(h1, h2, 0);
    gemm_pipe_kernel<N_CLS, HID_F>
        <<<HALF_N / 128, 256, SMEM_PIPE(N_CLS)>>>(h2, w2h, w2l, b2, h3, 0, HALF_N);

    cudaStreamWaitEvent(s_side, ev_g1, 0);
    spmm1_warp_kernel<<<(N_NODES - HALF_N) / 8, 256, 0, s_side>>>(h1, h2, HALF_N);
    gemm_pipe_kernel<N_CLS, HID_F>
        <<<(N_NODES - HALF_N + 127) / 128, 256, SMEM_PIPE(N_CLS), s_side>>>(
            h2, w2h, w2l, b2, h3, HALF_N, N_NODES);
    cudaEventRecord(ev_l2, s_side);

    // ---- final aggregation (needs all h3) ----
    cudaStreamWaitEvent(0, ev_l2, 0);
    spmm2_warp_kernel<<<(N_NODES + 7) / 8, 256>>>(h3, out);
}